// round 16
// baseline (speedup 1.0000x reference)
#include <cuda_runtime.h>
#include <cuda_fp16.h>
#include <math.h>

// Problem constants: preds [8,4,256,256] f32, targets [8,256,256] i32.
#define B 8
#define H 256
#define W 256
#define NCLS 3              // classes 1..3
#define NCB 24              // cb = (cls-1)*8 + b
#define IMG 65536           // H*W
#define NPIX 524288         // B*H*W
#define RWIN 6              // window radius; certified exact when min <= 36
#define THRESH 36.0f
#define OOB 49.0f           // out-of-window / out-of-bounds distance^2 (>36)
#define TY 4                // rows of output per block
#define HR (TY + 2 * RWIN)  // halo rows per block = 16
#define NBLK 512            // 8 b * 64 ytiles
#define BLK_PER_B 64
#define NFW (NCB * 8)       // flag words: 8 per (cls,b), bit = x
#define HOOBBITS 0x52205220u   // half2(49,49) bit pattern

// -------- scratch (__device__ globals; zero-initialized) --------
__device__ unsigned d_mask[NCLS * B * H * 8];  // row bitmasks (exact fallback)
__device__ unsigned d_flagw[NFW];    // flag bitmask: word (cb*8 + x/32), bit x%32
__device__ float d_partialS[3 * NBLK];  // per-block class sums (no contention)
__device__ int   d_partialC[3 * NBLK];  // per-block class pos counts
__device__ int   d_ctrb[B];          // per-batch completion counters
__device__ int   d_ctr;              // batch-level completion counter

// ---------------------------------------------------------------------
// Branchless windowed nearest-set-bit distance (radius 6), returns d in
// [0..7]; 7 means "beyond window" (d^2=49 > 36, never certified).
// win bits 0..12 correspond to positions x-6 .. x+6 (bit 6 = x).
// ---------------------------------------------------------------------
__device__ __forceinline__ int win_d_6(unsigned win) {
    unsigned t = win & 0x7Fu;                 // x-6..x
    int dl = __clz((t << 1) | 1u) - 24;       // 0..7
    unsigned t2 = (win >> 6) & 0x7Fu;         // x..x+6
    int dr = __ffs(t2 | 0x80u) - 1;           // 0..7
    return dl < dr ? dl : dr;
}

// half bit-pattern of small positive integer float (exact for our range)
__device__ __forceinline__ unsigned half_bits_of_int(int e2) {
    return (__float_as_uint((float)e2) >> 13) - (112u << 10);
}

// ---------------------------------------------------------------------
// Exact reference rowdist (full scans) — fallback only.
// ---------------------------------------------------------------------
__device__ int rowdist_full(const unsigned* m, int x, bool inv) {
    int w = x >> 5, b = x & 31;
    unsigned mw = inv ? ~m[w] : m[w];
    unsigned u = mw & (0xFFFFFFFFu >> (31 - b));
    int dl;
    if (u) {
        dl = b - (31 - __clz(u));
    } else {
        dl = 512 + x + 1;
        for (int i = w - 1; i >= 0; --i) {
            unsigned vi = inv ? ~m[i] : m[i];
            if (vi) { dl = x - (i * 32 + 31 - __clz(vi)); break; }
        }
    }
    unsigned u2 = mw & (0xFFFFFFFFu << b);
    int dr;
    if (u2) {
        dr = (__ffs(u2) - 1) - b;
    } else {
        dr = 512 + 256 - x;
        for (int i = w + 1; i < 8; ++i) {
            unsigned vi = inv ? ~m[i] : m[i];
            if (vi) { dr = i * 32 + (__ffs(vi) - 1) - x; break; }
        }
    }
    return dl < dr ? dl : dr;
}

// ---------------------------------------------------------------------
// Block-cooperative exact fallback for one flagged column (thread = y).
// Exact EDT from stored masks; the approximate path is reconstructed
// bit-exactly from the same masks (identical values to the
// nearest-opposite form in the main pass). Deterministic tree reduce.
// Never executes on typical inputs.
// ---------------------------------------------------------------------
__device__ void fix_column_coop(int cb, int x, const float* __restrict__ preds,
                                float* adj, float* red) {
    int cls = cb >> 3;      // 0-based
    int b = cb & 7;
    int y = threadIdx.x;
    __shared__ float gpe[256], gne[256], apx[256], anx[256];
    {
        unsigned mw[8];
#pragma unroll
        for (int i = 0; i < 8; ++i)
            mw[i] = d_mask[(cls * (B * H) + b * 256 + y) * 8 + i];
        int dp = rowdist_full(mw, x, false);
        int dn = rowdist_full(mw, x, true);
        gpe[y] = (float)(dp * dp);
        gne[y] = (float)(dn * dn);
        // reconstruct windowed (approximate) row dists exactly
        int s = x - RWIN, idx = s >> 5, off = s & 31;
        unsigned loP = (idx >= 0) ? mw[idx] : 0u;
        unsigned hiP = (idx + 1 < 8) ? mw[idx + 1] : 0u;
        unsigned loN = (idx >= 0) ? ~mw[idx] : 0u;
        unsigned hiN = (idx + 1 < 8) ? ~mw[idx + 1] : 0u;
        unsigned winP = (unsigned)(((((unsigned long long)hiP) << 32) | loP) >> off);
        unsigned winN = (unsigned)(((((unsigned long long)hiN) << 32) | loN) >> off);
        unsigned vmv = 0x1FFFu;
        if (x < RWIN) vmv = (vmv << (RWIN - x)) & 0x1FFFu;
        if (x > 255 - RWIN) vmv >>= (x - (255 - RWIN));
        int dP = win_d_6(winP & vmv);
        int dN = win_d_6(winN & vmv);
        apx[y] = (float)(dP * dP);
        anx[y] = (float)(dN * dN);
    }
    __syncthreads();
    float mpE = 1e30f, mnE = 1e30f;
    for (int yp = 0; yp < 256; ++yp) {
        float dy2 = (float)((y - yp) * (y - yp));
        mpE = fminf(mpE, gpe[yp] + dy2);
        mnE = fminf(mnE, gne[yp] + dy2);
    }
    bool pos = (gpe[y] == 0.0f);
    float exact = pos ? (1.0f - sqrtf(mnE)) : sqrtf(mpE);
    // approximate column min (window +-RWIN, OOB clamps)
    float mpA = 1e30f, mnA = 1e30f;
#pragma unroll
    for (int dy = -RWIN; dy <= RWIN; ++dy) {
        int gy = y + dy;
        float Sp = OOB, Sn = OOB;
        if (gy >= 0 && gy < H) { Sp = apx[gy]; Sn = anx[gy]; }
        float d2 = (float)(dy * dy);
        mpA = fminf(mpA, Sp + d2);
        mnA = fminf(mnA, Sn + d2);
    }
    float approx = pos ? (1.0f - sqrtf(mnA)) : sqrtf(mpA);
    float delta = 0.0f;
    if (exact != approx) {
        const float* p = preds + b * (4 * IMG) + (y << 8) + x;
        float e0 = __expf(p[0]);
        float e1 = __expf(p[IMG]);
        float e2 = __expf(p[2 * IMG]);
        float e3 = __expf(p[3 * IMG]);
        float inv = 1.0f / (e0 + e1 + e2 + e3);
        float pr = ((cls == 0) ? e1 : (cls == 1) ? e2 : e3) * inv;
        delta = (exact - approx) * pr;
    }
    __syncthreads();
    red[y] = delta;
    __syncthreads();
    for (int st = 128; st; st >>= 1) {
        if (y < st) red[y] += red[y + st];
        __syncthreads();
    }
    if (y == 0) adj[cls] += red[0];
    __syncthreads();
}

// ---------------------------------------------------------------------
// KALL: the whole problem in one kernel, all 3 classes per block.
// Grid: 8 b * 64 ytiles(4 rows) = 512 blocks, 256 threads.
// Body identical to the best-measured round-10 kernel. The reduction
// tail uses per-block partial arrays (plain STG, zero contention) and a
// two-level completion counter; the elected last block finalizes with
// warp-parallel deterministic sums.
// ---------------------------------------------------------------------
__global__ __launch_bounds__(256) void kall(const float* __restrict__ preds,
                                            const int* __restrict__ tg,
                                            float* __restrict__ out) {
    int tid = threadIdx.x;
    int lane = tid & 31;
    int wrp = tid >> 5;
    int b = blockIdx.x >> 6;
    int y0 = (blockIdx.x & 63) << 2;

    __shared__ unsigned gs[3][HR][256];   // (P,N) half2 bit patterns
    __shared__ float sm[8][3];
    __shared__ int smc[8][3];
    __shared__ float red[256];
    __shared__ float adj[3];
    __shared__ float sh_val[6];
    __shared__ int sh_flagged;
    __shared__ int sh_last;

    // validity masks per chunk (x-edge bits outside [0,255] must be 0)
    unsigned vm[8];
#pragma unroll
    for (int c = 0; c < 8; ++c) {
        int x = c * 32 + lane;
        unsigned v = 0x1FFFu;
        if (x < RWIN) v = (v << (RWIN - x)) & 0x1FFFu;
        if (x > 255 - RWIN) v >>= (x - (255 - RWIN));
        vm[c] = v;
    }

    // ---- row-transform phase: warp w handles halo rows 2w, 2w+1 ----
#pragma unroll
    for (int rr = 0; rr < 2; ++rr) {
        int r = wrp * 2 + rr;
        int gy = y0 - RWIN + r;
        bool valid = (gy >= 0) && (gy < H);       // warp-uniform
        if (valid) {
            int row = b * 256 + gy;
            int tv[8];
#pragma unroll
            for (int c = 0; c < 8; ++c) tv[c] = tg[row * 256 + c * 32 + lane];
#pragma unroll 1
            for (int cls = 1; cls <= NCLS; ++cls) {
                unsigned bw[8];
#pragma unroll
                for (int c = 0; c < 8; ++c) {
                    bw[c] = __ballot_sync(0xFFFFFFFFu, tv[c] == cls);
                    if (lane == c)
                        d_mask[((cls - 1) * (B * H) + row) * 8 + c] = bw[c];
                }
#pragma unroll
                for (int c = 0; c < 8; ++c) {
                    unsigned bp = (c > 0) ? bw[c - 1] : 0u;
                    unsigned bn = (c < 7) ? bw[c + 1] : 0u;
                    unsigned winP;
                    if (lane < RWIN)
                        winP = __funnelshift_r(bp, bw[c], lane + 32 - RWIN);
                    else
                        winP = __funnelshift_r(bw[c], bn, lane - RWIN);
                    bool own = (winP >> RWIN) & 1u;   // this pixel is pos
                    unsigned ownm = (unsigned)(-(int)own);
                    unsigned winX = (winP ^ ownm) & vm[c];
                    int d = win_d_6(winX);            // 1..7
                    unsigned hb = half_bits_of_int(d * d);
                    gs[cls - 1][r][c * 32 + lane] = own ? (hb << 16) : hb;
                }
            }
        } else {
#pragma unroll
            for (int cls = 0; cls < 3; ++cls)
#pragma unroll
                for (int c = 0; c < 8; ++c)
                    gs[cls][r][c * 32 + lane] = HOOBBITS;
        }
    }
    __syncthreads();

    // ---- column phase: thread = x; pairwise-min window ----
    float dmap[3][TY];
    int cnt[3] = {0, 0, 0};
    bool bad[3];

#pragma unroll
    for (int cls = 0; cls < 3; ++cls) {
        __half2 v[HR];
#pragma unroll
        for (int r = 0; r < HR; ++r) {
            unsigned raw = gs[cls][r][tid];
            v[r] = *reinterpret_cast<__half2*>(&raw);
        }
        __half2 mmax = __float2half2_rn(0.0f);
#pragma unroll
        for (int o = 0; o < TY; ++o) {
            __half2 m = v[o + RWIN];
#pragma unroll
            for (int k = 1; k <= RWIN; ++k) {
                __half2 kk = __float2half2_rn((float)(k * k));
                m = __hmin2(m, __hadd2(__hmin2(v[o + RWIN - k], v[o + RWIN + k]), kk));
            }
            mmax = __hmax2(mmax, m);
            bool pos = (__low2float(v[o + RWIN]) == 0.0f);
            float mp = __low2float(m);
            float mn = __high2float(m);
            dmap[cls][o] = pos ? (1.0f - sqrtf(mn)) : sqrtf(mp);
            cnt[cls] += pos ? 1 : 0;
        }
        bad[cls] = (fmaxf(__low2float(mmax), __high2float(mmax)) > THRESH);
    }
    // flag via warp ballot (atomic fires only when something is bad)
#pragma unroll
    for (int c = 0; c < 3; ++c) {
        unsigned bb = __ballot_sync(0xFFFFFFFFu, bad[c]);
        if (lane == 0 && bb)
            atomicOr(&d_flagw[(c * 8 + b) * 8 + wrp], bb);
    }

    // ---- softmax + dot with dmap ----
    float s[3] = {0.f, 0.f, 0.f};
    const float* pb = preds + b * (4 * IMG) + (y0 << 8) + tid;
#pragma unroll
    for (int o = 0; o < TY; ++o) {
        const float* p = pb + (o << 8);
        float e0 = __expf(p[0]);
        float e1 = __expf(p[IMG]);
        float e2 = __expf(p[2 * IMG]);
        float e3 = __expf(p[3 * IMG]);
        float inv = 1.0f / (e0 + e1 + e2 + e3);
        s[0] += dmap[0][o] * (e1 * inv);
        s[1] += dmap[1][o] * (e2 * inv);
        s[2] += dmap[2][o] * (e3 * inv);
    }

    // ---- block reduction ----
#pragma unroll
    for (int off = 16; off; off >>= 1) {
#pragma unroll
        for (int c = 0; c < 3; ++c) {
            s[c] += __shfl_down_sync(0xFFFFFFFFu, s[c], off);
            cnt[c] += __shfl_down_sync(0xFFFFFFFFu, cnt[c], off);
        }
    }
    if (lane == 0) {
#pragma unroll
        for (int c = 0; c < 3; ++c) { sm[wrp][c] = s[c]; smc[wrp][c] = cnt[c]; }
    }
    __syncthreads();
    if (tid < 3) {
        float t = 0.0f; int ci = 0;
#pragma unroll
        for (int i = 0; i < 8; ++i) { t += sm[i][tid]; ci += smc[i][tid]; }
        d_partialS[tid * NBLK + blockIdx.x] = t;    // plain STG, no contention
        d_partialC[tid * NBLK + blockIdx.x] = ci;
    }
    __syncthreads();
    if (tid == 0) {
        __threadfence();
        int last = 0;
        if (atomicAdd(&d_ctrb[b], 1) == BLK_PER_B - 1) {       // last in batch
            if (atomicAdd(&d_ctr, 1) == B - 1) last = 1;       // last overall
        }
        sh_last = last;
    }
    __syncthreads();
    if (!sh_last) return;

    // ================= elected last block: finalize =================
    __threadfence();                    // acquire: see all blocks' writes
    if (tid == 0) sh_flagged = 0;
    if (tid < 3) adj[tid] = 0.0f;
    __syncthreads();
    if (wrp < 6) {
        // warps 0-2: class sums; warps 3-5: class counts. Fixed order ->
        // deterministic across replays.
        float v = 0.0f;
        if (wrp < 3) {
            for (int i = lane; i < NBLK; i += 32) v += d_partialS[wrp * NBLK + i];
        } else {
            for (int i = lane; i < NBLK; i += 32)
                v += (float)d_partialC[(wrp - 3) * NBLK + i];
        }
#pragma unroll
        for (int o = 16; o; o >>= 1) v += __shfl_down_sync(0xFFFFFFFFu, v, o);
        if (lane == 0) sh_val[wrp] = v;
    } else {
        int t = tid - 192, f = 0;
        for (int i = t; i < NFW; i += 64) f |= (d_flagw[i] != 0u);
        if (f) atomicOr(&sh_flagged, 1);
    }
    __syncthreads();
    if (sh_flagged) {                  // block-uniform; never on typical inputs
        for (int i = 0; i < NFW; ++i) {
            unsigned wv = d_flagw[i];
            while (wv) {
                int bit = __ffs(wv) - 1;
                wv &= wv - 1;
                fix_column_coop(i >> 3, (i & 7) * 32 + bit, preds, adj, red);
            }
        }
    }
    __syncthreads();
    // consume-then-clear state for the next graph replay
    if (tid < NFW) d_flagw[tid] = 0;
    if (tid >= 248 && tid < 256) d_ctrb[tid - 248] = 0;
    if (tid == 247) d_ctr = 0;
    if (tid == 0) {
        float total = 0.0f, count = 0.0f;
        for (int c = 0; c < 3; ++c) {
            if (sh_val[3 + c] > 0.0f) {
                total += (sh_val[c] + adj[c]) * (1.0f / (float)NPIX);
                count += 1.0f;
            }
        }
        out[0] = (count > 0.0f) ? (total / count) : 0.0f;
    }
}

extern "C" void kernel_launch(void* const* d_in, const int* in_sizes, int n_in,
                              void* d_out, int out_size) {
    const float* preds = (const float*)d_in[0];
    const int* targets = (const int*)d_in[1];
    float* out = (float*)d_out;

    kall<<<NBLK, 256>>>(preds, targets, out);
}

// round 17
// speedup vs baseline: 1.2931x; 1.2931x over previous
#include <cuda_runtime.h>
#include <cuda_fp16.h>
#include <math.h>

// Problem constants: preds [8,4,256,256] f32, targets [8,256,256] i32.
#define B 8
#define H 256
#define W 256
#define NCLS 3              // classes 1..3
#define NCB 24              // cb = (cls-1)*8 + b
#define IMG 65536           // H*W
#define NPIX 524288         // B*H*W
#define RWIN 6              // window radius; certified exact when min <= 36
#define THRESH 36.0f
#define OOB 49.0f           // out-of-window / out-of-bounds distance^2 (>36)
#define TY 4                // rows of output per block
#define HR (TY + 2 * RWIN)  // halo rows per block = 16
#define NBLK 512            // 8 b * 64 ytiles
#define NFW (NCB * 8)       // flag words: 8 per (cls,b), bit = x
#define FPSCALE 4294967296.0   // 2^32 fixed-point scale
#define HOOBBITS 0x52205220u   // half2(49,49) bit pattern

// -------- scratch (__device__ globals; zero-initialized) --------
__device__ unsigned d_flagw[NFW];    // flag bitmask: word (cb*8 + x/32), bit x%32
__device__ long long d_sumll[3];     // fixed-point class sums (deterministic)
__device__ int   d_cntg[3];          // class pos counts
__device__ int   d_ctr;              // completed-block counter

// ---------------------------------------------------------------------
// Branchless windowed nearest-set-bit distance (radius 6), returns d in
// [0..7]; 7 means "beyond window" (d^2=49 > 36, never certified).
// win bits 0..12 correspond to positions x-6 .. x+6 (bit 6 = x).
// ---------------------------------------------------------------------
__device__ __forceinline__ int win_d_6(unsigned win) {
    unsigned t = win & 0x7Fu;                 // x-6..x
    int dl = __clz((t << 1) | 1u) - 24;       // 0..7
    unsigned t2 = (win >> 6) & 0x7Fu;         // x..x+6
    int dr = __ffs(t2 | 0x80u) - 1;           // 0..7
    return dl < dr ? dl : dr;
}

// half bit-pattern of small positive integer float (exact for our range)
__device__ __forceinline__ unsigned half_bits_of_int(int e2) {
    return (__float_as_uint((float)e2) >> 13) - (112u << 10);
}

// ---------------------------------------------------------------------
// Exact reference rowdist (full scans) — fallback only.
// ---------------------------------------------------------------------
__device__ int rowdist_full(const unsigned* m, int x, bool inv) {
    int w = x >> 5, b = x & 31;
    unsigned mw = inv ? ~m[w] : m[w];
    unsigned u = mw & (0xFFFFFFFFu >> (31 - b));
    int dl;
    if (u) {
        dl = b - (31 - __clz(u));
    } else {
        dl = 512 + x + 1;
        for (int i = w - 1; i >= 0; --i) {
            unsigned vi = inv ? ~m[i] : m[i];
            if (vi) { dl = x - (i * 32 + 31 - __clz(vi)); break; }
        }
    }
    unsigned u2 = mw & (0xFFFFFFFFu << b);
    int dr;
    if (u2) {
        dr = (__ffs(u2) - 1) - b;
    } else {
        dr = 512 + 256 - x;
        for (int i = w + 1; i < 8; ++i) {
            unsigned vi = inv ? ~m[i] : m[i];
            if (vi) { dr = i * 32 + (__ffs(vi) - 1) - x; break; }
        }
    }
    return dl < dr ? dl : dr;
}

// ---------------------------------------------------------------------
// Block-cooperative exact fallback for one flagged column (thread = y).
// Row bitmasks are rebuilt directly from the targets input (no stored
// masks needed). Exact EDT, plus bit-exact reconstruction of the
// approximate (windowed, clamped) path. Deterministic tree reduce.
// Never executes on typical inputs.
// ---------------------------------------------------------------------
__device__ void fix_column_coop(int cb, int x, const float* __restrict__ preds,
                                const int* __restrict__ tg,
                                float* adj, float* red) {
    int cls = cb >> 3;      // 0-based
    int b = cb & 7;
    int y = threadIdx.x;
    __shared__ float gpe[256], gne[256], apx[256], anx[256];
    {
        // rebuild this row's class bitmask from targets
        unsigned mw[8];
        const int* trow = tg + (b * 256 + y) * 256;
        for (int i = 0; i < 8; ++i) {
            unsigned w = 0u;
            for (int j = 0; j < 32; ++j)
                if (trow[i * 32 + j] == cls + 1) w |= (1u << j);
            mw[i] = w;
        }
        int dp = rowdist_full(mw, x, false);
        int dn = rowdist_full(mw, x, true);
        gpe[y] = (float)(dp * dp);
        gne[y] = (float)(dn * dn);
        // reconstruct windowed (approximate) row dists exactly
        int s = x - RWIN, idx = s >> 5, off = s & 31;
        unsigned loP = (idx >= 0) ? mw[idx] : 0u;
        unsigned hiP = (idx + 1 < 8) ? mw[idx + 1] : 0u;
        unsigned loN = (idx >= 0) ? ~mw[idx] : 0u;
        unsigned hiN = (idx + 1 < 8) ? ~mw[idx + 1] : 0u;
        unsigned winP = (unsigned)(((((unsigned long long)hiP) << 32) | loP) >> off);
        unsigned winN = (unsigned)(((((unsigned long long)hiN) << 32) | loN) >> off);
        unsigned vmv = 0x1FFFu;
        if (x < RWIN) vmv = (vmv << (RWIN - x)) & 0x1FFFu;
        if (x > 255 - RWIN) vmv >>= (x - (255 - RWIN));
        int dP = win_d_6(winP & vmv);
        int dN = win_d_6(winN & vmv);
        apx[y] = (float)(dP * dP);
        anx[y] = (float)(dN * dN);
    }
    __syncthreads();
    float mpE = 1e30f, mnE = 1e30f;
    for (int yp = 0; yp < 256; ++yp) {
        float dy2 = (float)((y - yp) * (y - yp));
        mpE = fminf(mpE, gpe[yp] + dy2);
        mnE = fminf(mnE, gne[yp] + dy2);
    }
    bool pos = (gpe[y] == 0.0f);
    float exact = pos ? (1.0f - sqrtf(mnE)) : sqrtf(mpE);
    // approximate column min (window +-RWIN, OOB clamps)
    float mpA = 1e30f, mnA = 1e30f;
#pragma unroll
    for (int dy = -RWIN; dy <= RWIN; ++dy) {
        int gy = y + dy;
        float Sp = OOB, Sn = OOB;
        if (gy >= 0 && gy < H) { Sp = apx[gy]; Sn = anx[gy]; }
        float d2 = (float)(dy * dy);
        mpA = fminf(mpA, Sp + d2);
        mnA = fminf(mnA, Sn + d2);
    }
    float approx = pos ? (1.0f - sqrtf(mnA)) : sqrtf(mpA);
    float delta = 0.0f;
    if (exact != approx) {
        const float* p = preds + b * (4 * IMG) + (y << 8) + x;
        float e0 = __expf(p[0]);
        float e1 = __expf(p[IMG]);
        float e2 = __expf(p[2 * IMG]);
        float e3 = __expf(p[3 * IMG]);
        float inv = __fdividef(1.0f, e0 + e1 + e2 + e3);
        float pr = ((cls == 0) ? e1 : (cls == 1) ? e2 : e3) * inv;
        delta = (exact - approx) * pr;
    }
    __syncthreads();
    red[y] = delta;
    __syncthreads();
    for (int st = 128; st; st >>= 1) {
        if (y < st) red[y] += red[y + st];
        __syncthreads();
    }
    if (y == 0) adj[cls] += red[0];
    __syncthreads();
}

// ---------------------------------------------------------------------
// KALL: the whole problem in one kernel, all 3 classes per block.
// Grid: 8 b * 64 ytiles(4 rows) = 512 blocks, 256 threads.
// Row phase: 8 warps x 2 halo rows, register ballots + funnel shifts,
// nearest-opposite window, half-bit packing into smem (no mask stores).
// Column phase: thread = x, pairwise-min half2 window. Fast-div softmax
// + block reduce + deterministic fixed-point atomics; counter-elected
// last block finalizes (flag scan, fallback, has/count, output, reset).
// ---------------------------------------------------------------------
__global__ __launch_bounds__(256) void kall(const float* __restrict__ preds,
                                            const int* __restrict__ tg,
                                            float* __restrict__ out) {
    int tid = threadIdx.x;
    int lane = tid & 31;
    int wrp = tid >> 5;
    int b = blockIdx.x >> 6;
    int y0 = (blockIdx.x & 63) << 2;

    __shared__ unsigned gs[3][HR][256];   // (P,N) half2 bit patterns
    __shared__ float sm[8][3];
    __shared__ int smc[8][3];
    __shared__ float red[256];
    __shared__ float adj[3];
    __shared__ int sh_flagged;
    __shared__ int sh_last;

    // validity masks per chunk (x-edge bits outside [0,255] must be 0)
    unsigned vm[8];
#pragma unroll
    for (int c = 0; c < 8; ++c) {
        int x = c * 32 + lane;
        unsigned v = 0x1FFFu;
        if (x < RWIN) v = (v << (RWIN - x)) & 0x1FFFu;
        if (x > 255 - RWIN) v >>= (x - (255 - RWIN));
        vm[c] = v;
    }

    // ---- row-transform phase: warp w handles halo rows 2w, 2w+1 ----
#pragma unroll
    for (int rr = 0; rr < 2; ++rr) {
        int r = wrp * 2 + rr;
        int gy = y0 - RWIN + r;
        bool valid = (gy >= 0) && (gy < H);       // warp-uniform
        if (valid) {
            int row = b * 256 + gy;
            int tv[8];
#pragma unroll
            for (int c = 0; c < 8; ++c) tv[c] = tg[row * 256 + c * 32 + lane];
#pragma unroll 1
            for (int cls = 1; cls <= NCLS; ++cls) {
                unsigned bw[8];
#pragma unroll
                for (int c = 0; c < 8; ++c)
                    bw[c] = __ballot_sync(0xFFFFFFFFu, tv[c] == cls);
#pragma unroll
                for (int c = 0; c < 8; ++c) {
                    unsigned bp = (c > 0) ? bw[c - 1] : 0u;
                    unsigned bn = (c < 7) ? bw[c + 1] : 0u;
                    unsigned winP;
                    if (lane < RWIN)
                        winP = __funnelshift_r(bp, bw[c], lane + 32 - RWIN);
                    else
                        winP = __funnelshift_r(bw[c], bn, lane - RWIN);
                    bool own = (winP >> RWIN) & 1u;   // this pixel is pos
                    unsigned ownm = (unsigned)(-(int)own);
                    unsigned winX = (winP ^ ownm) & vm[c];
                    int d = win_d_6(winX);            // 1..7
                    unsigned hb = half_bits_of_int(d * d);
                    gs[cls - 1][r][c * 32 + lane] = own ? (hb << 16) : hb;
                }
            }
        } else {
#pragma unroll
            for (int cls = 0; cls < 3; ++cls)
#pragma unroll
                for (int c = 0; c < 8; ++c)
                    gs[cls][r][c * 32 + lane] = HOOBBITS;
        }
    }
    __syncthreads();

    // ---- column phase: thread = x; pairwise-min window ----
    float dmap[3][TY];
    int cnt[3] = {0, 0, 0};
    bool bad[3];

#pragma unroll
    for (int cls = 0; cls < 3; ++cls) {
        __half2 v[HR];
#pragma unroll
        for (int r = 0; r < HR; ++r) {
            unsigned raw = gs[cls][r][tid];
            v[r] = *reinterpret_cast<__half2*>(&raw);
        }
        __half2 mmax = __float2half2_rn(0.0f);
#pragma unroll
        for (int o = 0; o < TY; ++o) {
            __half2 m = v[o + RWIN];
#pragma unroll
            for (int k = 1; k <= RWIN; ++k) {
                __half2 kk = __float2half2_rn((float)(k * k));
                m = __hmin2(m, __hadd2(__hmin2(v[o + RWIN - k], v[o + RWIN + k]), kk));
            }
            mmax = __hmax2(mmax, m);
            bool pos = (__low2float(v[o + RWIN]) == 0.0f);
            float mp = __low2float(m);
            float mn = __high2float(m);
            dmap[cls][o] = pos ? (1.0f - sqrtf(mn)) : sqrtf(mp);
            cnt[cls] += pos ? 1 : 0;
        }
        bad[cls] = (fmaxf(__low2float(mmax), __high2float(mmax)) > THRESH);
    }
    // flag via warp ballot (atomic fires only when something is bad)
#pragma unroll
    for (int c = 0; c < 3; ++c) {
        unsigned bb = __ballot_sync(0xFFFFFFFFu, bad[c]);
        if (lane == 0 && bb)
            atomicOr(&d_flagw[(c * 8 + b) * 8 + wrp], bb);
    }

    // ---- softmax + dot with dmap (fast division) ----
    float s[3] = {0.f, 0.f, 0.f};
    const float* pb = preds + b * (4 * IMG) + (y0 << 8) + tid;
#pragma unroll
    for (int o = 0; o < TY; ++o) {
        const float* p = pb + (o << 8);
        float e0 = __expf(p[0]);
        float e1 = __expf(p[IMG]);
        float e2 = __expf(p[2 * IMG]);
        float e3 = __expf(p[3 * IMG]);
        float inv = __fdividef(1.0f, e0 + e1 + e2 + e3);
        s[0] += dmap[0][o] * (e1 * inv);
        s[1] += dmap[1][o] * (e2 * inv);
        s[2] += dmap[2][o] * (e3 * inv);
    }

    // ---- block reduction ----
#pragma unroll
    for (int off = 16; off; off >>= 1) {
#pragma unroll
        for (int c = 0; c < 3; ++c) {
            s[c] += __shfl_down_sync(0xFFFFFFFFu, s[c], off);
            cnt[c] += __shfl_down_sync(0xFFFFFFFFu, cnt[c], off);
        }
    }
    if (lane == 0) {
#pragma unroll
        for (int c = 0; c < 3; ++c) { sm[wrp][c] = s[c]; smc[wrp][c] = cnt[c]; }
    }
    __syncthreads();
    if (tid < 3) {
        float t = 0.0f; int ci = 0;
#pragma unroll
        for (int i = 0; i < 8; ++i) { t += sm[i][tid]; ci += smc[i][tid]; }
        long long q = __double2ll_rn((double)t * FPSCALE);
        atomicAdd((unsigned long long*)&d_sumll[tid], (unsigned long long)q);
        atomicAdd(&d_cntg[tid], ci);
    }
    __syncthreads();
    if (tid == 0) {
        __threadfence();
        sh_last = (atomicAdd(&d_ctr, 1) == NBLK - 1) ? 1 : 0;
    }
    __syncthreads();
    if (!sh_last) return;

    // ================= last block: finalize =================
    __threadfence();                    // acquire: see all blocks' writes
    if (tid == 0) sh_flagged = 0;
    if (tid < 3) adj[tid] = 0.0f;
    __syncthreads();
    if (tid < NFW) {
        if (d_flagw[tid]) atomicOr(&sh_flagged, 1);
    }
    __syncthreads();
    if (sh_flagged) {                  // block-uniform; never on typical inputs
        for (int i = 0; i < NFW; ++i) {
            unsigned wv = d_flagw[i];
            while (wv) {
                int bit = __ffs(wv) - 1;
                wv &= wv - 1;
                fix_column_coop(i >> 3, (i & 7) * 32 + bit, preds, tg, adj, red);
            }
        }
    }
    __syncthreads();
    // consume-then-clear flags for the next graph replay
    if (tid < NFW) d_flagw[tid] = 0;
    if (tid == 0) {
        float total = 0.0f, count = 0.0f;
        for (int c = 0; c < 3; ++c) {
            if (d_cntg[c] > 0) {
                float tc = (float)((double)d_sumll[c] / FPSCALE) + adj[c];
                total += tc * (1.0f / (float)NPIX);
                count += 1.0f;
            }
            d_sumll[c] = 0;            // reset state for next replay
            d_cntg[c] = 0;
        }
        d_ctr = 0;
        out[0] = (count > 0.0f) ? (total / count) : 0.0f;
    }
}

extern "C" void kernel_launch(void* const* d_in, const int* in_sizes, int n_in,
                              void* d_out, int out_size) {
    const float* preds = (const float*)d_in[0];
    const int* targets = (const int*)d_in[1];
    float* out = (float*)d_out;

    kall<<<NBLK, 256>>>(preds, targets, out);
}